// round 12
// baseline (speedup 1.0000x reference)
#include <cuda_runtime.h>
#include <math.h>
#include <stdint.h>

// ---------------- problem constants ----------------
#define E_TOT   400000
#define TILE    64
#define NBLK    (E_TOT / TILE)   // 6250
#define NCLS    64
#define HSZ     32
#define NTHREADS 256

// ---------------- smem layout (from 1024-aligned base) ----------------
#define OFF_A1   0u          // A level-1 int8: 64 rows x 256B = 16KB
#define OFF_A2   16384u      // A level-2 int8: 16KB
#define OFF_B    32768u      // 4 groups x 2 bufs x 4KB = 32KB (buf: b1@+0, b2@+2048)
#define OFF_Q    65536u      // q f32 [64][33] = 8448B
#define OFF_EW   73984u      // ew f32 [64]
#define OFF_GID  74240u      // gid int [64]
#define OFF_SC   74496u      // 8 int slots (float-bit maxima)
#define OFF_KSM  32768u      // k  f32 [64][33] (alias over B, post-GEMM)
#define OFF_WSM  41216u      // xn f32 [64][65] (alias over B, post-GEMM)
#define SMEM_REQ (74528u + 1024u)

#define QC (1.f / (127.f * 127.f * 128.f))

// ---------------- pre-quantized weights (two-level int8) ----------------
// chunk (Kc=32): N*32 bytes; byte pos in chunk = n*32 + ((k&31) ^ (((n>>2)&1)<<4))
__device__ signed char gW0b1[65536], gW0b2[65536];   // L0: 8 chunks x 8KB
__device__ signed char gW1b1[65536], gW1b2[65536];   // L1
__device__ signed char gQb1[8192],  gQb2[8192];      // q image N=32 (W2@Wqk)
__device__ signed char gNb1[24576], gNb2[24576];     // final N=96 [W2 | W2@Wk]
__device__ float gS0[256], gS1[256], gSf[128];       // per-col scales (abs max)
__device__ float gFold[256 * 128];                   // folded final weights f32

// ---------------- helpers ----------------
__device__ __forceinline__ uint32_t smem_u32(const void* p) {
    uint32_t a;
    asm("{ .reg .u64 t; cvta.to.shared.u64 t, %1; cvt.u32.u64 %0, t; }"
        : "=r"(a) : "l"(p));
    return a;
}
__device__ __forceinline__ void ldsm4(uint32_t addr, uint32_t& r0, uint32_t& r1,
                                      uint32_t& r2, uint32_t& r3) {
    asm volatile("ldmatrix.sync.aligned.m8n8.x4.shared.b16 {%0,%1,%2,%3}, [%4];"
                 : "=r"(r0), "=r"(r1), "=r"(r2), "=r"(r3) : "r"(addr));
}
__device__ __forceinline__ void mma_s8(int* d, const uint32_t* a,
                                       uint32_t b0, uint32_t b1) {
    asm volatile("mma.sync.aligned.m16n8k32.row.col.s32.s8.s8.s32 "
                 "{%0,%1,%2,%3}, {%4,%5,%6,%7}, {%8,%9}, {%0,%1,%2,%3};"
                 : "+r"(d[0]), "+r"(d[1]), "+r"(d[2]), "+r"(d[3])
                 : "r"(a[0]), "r"(a[1]), "r"(a[2]), "r"(a[3]), "r"(b0), "r"(b1));
}
__device__ __forceinline__ void cpa16(uint32_t s, const void* g) {
    asm volatile("cp.async.cg.shared.global [%0], [%1], 16;" :: "r"(s), "l"(g));
}
#define CP_COMMIT() asm volatile("cp.async.commit_group;")
#define CP_WAIT1()  asm volatile("cp.async.wait_group 1;" ::: "memory")
#define BARG(id)    asm volatile("bar.sync %0, 64;" :: "r"(id) : "memory")

// A int8 plane: 256B rows, conflict-free ldmatrix (kb = byte 0..255)
__device__ __forceinline__ uint32_t apos8(int row, int kb) {
    return (uint32_t)row * 256u + (uint32_t)(kb ^ ((row & 7) << 4));
}
// B int8 slice: 32B rows
__device__ __forceinline__ uint32_t bpos8(int r, int t) {
    return (uint32_t)r * 32u + (uint32_t)(t ^ (((r >> 2) & 1) << 4));
}
__device__ __forceinline__ void quant2(float x, float inv, int& q1, int& q2) {
    float v = x * inv;
    float r = rintf(v);
    q1 = (int)r;
    q2 = (int)rintf((v - r) * 128.f);
}
__device__ __forceinline__ uint32_t pk2(int hi, int lo) {
    uint32_t r; int z = 0;
    asm("cvt.pack.sat.s8.s32.b32 %0, %1, %2, %3;" : "=r"(r) : "r"(hi), "r"(lo), "r"(z));
    return r;   // byte0 = lo, byte1 = hi
}
__device__ __forceinline__ uint32_t pk4(int v3, int v2, int v1, int v0) {
    uint32_t t; int z = 0;
    asm("cvt.pack.sat.s8.s32.b32 %0, %1, %2, %3;" : "=r"(t) : "r"(v3), "r"(v2), "r"(z));
    uint32_t r;
    asm("cvt.pack.sat.s8.s32.b32 %0, %1, %2, %3;" : "=r"(r) : "r"(v1), "r"(v0), "r"(t));
    return r;   // memory bytes v0,v1,v2,v3
}

// ---------------- setup kernels ----------------
__global__ void prep_fold(const float* __restrict__ W2, const float* __restrict__ Wqk,
                          const float* __restrict__ Wk) {
    int idx = blockIdx.x * blockDim.x + threadIdx.x;   // 32768
    int k = idx >> 7, n = idx & 127;
    float v;
    if (n < 32) {
        v = 0.f;
        for (int c = 0; c < 64; c++) v += W2[k * 64 + c] * Wqk[c * 32 + n];
    } else if (n < 96) {
        v = W2[k * 64 + (n - 32)];
    } else {
        v = 0.f;
        for (int c = 0; c < 64; c++) v += W2[k * 64 + c] * Wk[c * 32 + (n - 96)];
    }
    gFold[k * 128 + n] = v;
}
__global__ void prep_scales(const float* __restrict__ W0, const float* __restrict__ W1) {
    int t = blockIdx.x * blockDim.x + threadIdx.x;     // 768, use 640
    if (t < 256) {
        float m = 0.f;
        for (int k = 0; k < 256; k++) m = fmaxf(m, fabsf(W0[k * 256 + t]));
        gS0[t] = m;
    } else if (t < 512) {
        int n = t - 256;
        float m = 0.f;
        for (int k = 0; k < 256; k++) m = fmaxf(m, fabsf(W1[k * 256 + n]));
        gS1[n] = m;
    } else if (t < 640) {
        int n = t - 512;
        float m = 0.f;
        for (int k = 0; k < 256; k++) m = fmaxf(m, fabsf(gFold[k * 128 + n]));
        gSf[n] = m;
    }
}
__global__ void prep_quant(const float* __restrict__ W0, const float* __restrict__ W1) {
    int idx = blockIdx.x * blockDim.x + threadIdx.x;   // 163840
    if (idx < 131072) {
        int layer = idx >> 16, rem = idx & 65535;
        int k = rem >> 8, n = rem & 255;
        const float* W = layer ? W1 : W0;
        float m = layer ? gS1[n] : gS0[n];
        float inv = (m > 0.f) ? 127.f / m : 0.f;
        int q1, q2;
        quant2(W[k * 256 + n], inv, q1, q2);
        uint32_t pos = (uint32_t)(k >> 5) * 8192u + bpos8(n, k & 31);
        (layer ? gW1b1 : gW0b1)[pos] = (signed char)q1;
        (layer ? gW1b2 : gW0b2)[pos] = (signed char)q2;
    } else {
        int rem = idx - 131072;                        // 32768
        int k = rem >> 7, n = rem & 127;
        float m = gSf[n];
        float inv = (m > 0.f) ? 127.f / m : 0.f;
        int q1, q2;
        quant2(gFold[k * 128 + n], inv, q1, q2);
        if (n < 32) {
            uint32_t pos = (uint32_t)(k >> 5) * 1024u + bpos8(n, k & 31);
            gQb1[pos] = (signed char)q1; gQb2[pos] = (signed char)q2;
        } else {
            uint32_t pos = (uint32_t)(k >> 5) * 3072u + bpos8(n - 32, k & 31);
            gNb1[pos] = (signed char)q1; gNb2[pos] = (signed char)q2;
        }
    }
}
__global__ void zero_out_kernel(float* __restrict__ out, int n) {
    int i = blockIdx.x * blockDim.x + threadIdx.x;
    if (i < n) out[i] = 0.f;
}

// ---------------- GEMM compute ----------------
// phase A: acc += a1 @ b1
template<int NF>
__device__ __forceinline__ void comp_A(uint32_t SB, uint32_t buf, int (*d)[4],
                                       int m0, int lane, int kb0) {
    const int lr = lane & 15;
    const int lh = (lane >> 4) * 16;
    uint32_t a1[2][4];
#pragma unroll
    for (int i = 0; i < 2; i++)
        ldsm4(SB + OFF_A1 + apos8(m0 + 16 * i + lr, kb0 + lh),
              a1[i][0], a1[i][1], a1[i][2], a1[i][3]);
#pragma unroll
    for (int jj = 0; jj < NF / 2; jj++) {
        uint32_t r0, r1, r2, r3;
        ldsm4(buf + bpos8(jj * 16 + lr, lh), r0, r1, r2, r3);
#pragma unroll
        for (int i = 0; i < 2; i++) {
            mma_s8(d[i * NF + 2 * jj],     a1[i], r0, r2);
            mma_s8(d[i * NF + 2 * jj + 1], a1[i], r1, r3);
        }
    }
}
// phase B: acc += a1 @ b2 + a2 @ b1
template<int NF>
__device__ __forceinline__ void comp_B(uint32_t SB, uint32_t buf, int (*d)[4],
                                       int m0, int lane, int kb0) {
    const int lr = lane & 15;
    const int lh = (lane >> 4) * 16;
    uint32_t a1[2][4], a2[2][4];
#pragma unroll
    for (int i = 0; i < 2; i++) {
        uint32_t ao = apos8(m0 + 16 * i + lr, kb0 + lh);
        ldsm4(SB + OFF_A1 + ao, a1[i][0], a1[i][1], a1[i][2], a1[i][3]);
        ldsm4(SB + OFF_A2 + ao, a2[i][0], a2[i][1], a2[i][2], a2[i][3]);
    }
#pragma unroll
    for (int jj = 0; jj < NF / 2; jj++) {
        uint32_t p0, p1, p2, p3, q0, q1, q2, q3;
        ldsm4(buf + bpos8(jj * 16 + lr, lh), p0, p1, p2, p3);             // b1
        ldsm4(buf + 2048u + bpos8(jj * 16 + lr, lh), q0, q1, q2, q3);     // b2
#pragma unroll
        for (int i = 0; i < 2; i++) {
            mma_s8(d[i * NF + 2 * jj],     a1[i], q0, q2);
            mma_s8(d[i * NF + 2 * jj],     a2[i], p0, p2);
            mma_s8(d[i * NF + 2 * jj + 1], a1[i], q1, q3);
            mma_s8(d[i * NF + 2 * jj + 1], a2[i], p1, p3);
        }
    }
}

__device__ __forceinline__ void cpyA(uint32_t dst, const char* s, int bytes, int lt) {
    for (int i = lt * 16; i < bytes; i += 1024) cpa16(dst + i, s + i);
    CP_COMMIT();
}
__device__ __forceinline__ void cpyB(uint32_t dst, const char* s1, const char* s2,
                                     int bytes, int lt) {
    for (int i = lt * 16; i < bytes; i += 1024) {
        cpa16(dst + i, s1 + i);
        cpa16(dst + 2048u + i, s2 + i);
    }
    CP_COMMIT();
}

// layer: phase A (b1 only) over nch chunks, acc*=128, phase B (b1+b2).
// pre: phase-A chunks 0,1 already committed. Tail of B prefetches next image.
template<int NF>
__device__ void layer_q(uint32_t SB, uint32_t gb, const char* b1, const char* b2,
                        int chunkB, int sliceOff, int nch,
                        const char* nx1, int nxChunkB, int nxSliceOff, int nxSliceB,
                        int (*d)[4], int m0, int kbase, int lane, int lt, int barid) {
    const int sliceB = NF * 256;
#pragma unroll 1
    for (int c = 0; c < nch; c++) {
        CP_WAIT1();
        BARG(barid);
        comp_A<NF>(SB, gb + (c & 1) * 4096u, d, m0, lane, kbase + c * 32);
        BARG(barid);
        if (c < nch - 2) {
            cpyA(gb + (c & 1) * 4096u, b1 + (c + 2) * chunkB + sliceOff, sliceB, lt);
        } else {
            int cc = c - (nch - 2);
            cpyB(gb + (c & 1) * 4096u, b1 + cc * chunkB + sliceOff,
                 b2 + cc * chunkB + sliceOff, sliceB, lt);
        }
    }
#pragma unroll
    for (int i = 0; i < 2 * NF; i++) {
        d[i][0] *= 128; d[i][1] *= 128; d[i][2] *= 128; d[i][3] *= 128;
    }
#pragma unroll 1
    for (int c = 0; c < nch; c++) {
        CP_WAIT1();
        BARG(barid);
        comp_B<NF>(SB, gb + (c & 1) * 4096u, d, m0, lane, kbase + c * 32);
        BARG(barid);
        if (c < nch - 2) {
            cpyB(gb + (c & 1) * 4096u, b1 + (c + 2) * chunkB + sliceOff,
                 b2 + (c + 2) * chunkB + sliceOff, sliceB, lt);
        } else if (nxSliceB) {
            int cc = c - (nch - 2);
            cpyA(gb + (c & 1) * 4096u, nx1 + cc * nxChunkB + nxSliceOff, nxSliceB, lt);
        } else {
            CP_COMMIT();
        }
    }
}

// epilogue: scale->relu->tile max->two-level int8 requantize into A planes
__device__ void epi_q(char* smc, int (*d)[4], int m0, int n0, int lane,
                      float sA, const float* __restrict__ gS, int* slot) {
    float sc = sA * QC;
    float mloc = 0.f;
#pragma unroll
    for (int j = 0; j < 8; j++) {
        int n = n0 + j * 8 + 2 * (lane & 3);
        float s0 = __ldg(gS + n) * sc, s1 = __ldg(gS + n + 1) * sc;
#pragma unroll
        for (int i = 0; i < 2; i++) {
            int* dd = d[i * 8 + j];
            float x0 = fmaxf((float)dd[0] * s0, 0.f);
            float x1 = fmaxf((float)dd[1] * s1, 0.f);
            float x2 = fmaxf((float)dd[2] * s0, 0.f);
            float x3 = fmaxf((float)dd[3] * s1, 0.f);
            mloc = fmaxf(mloc, fmaxf(fmaxf(x0, x1), fmaxf(x2, x3)));
            dd[0] = __float_as_int(x0); dd[1] = __float_as_int(x1);
            dd[2] = __float_as_int(x2); dd[3] = __float_as_int(x3);
        }
    }
#pragma unroll
    for (int s = 16; s; s >>= 1) mloc = fmaxf(mloc, __shfl_xor_sync(0xffffffffu, mloc, s));
    if (lane == 0) atomicMax(slot, __float_as_int(mloc));
    __syncthreads();                 // also: all layer reads of A done before writes
    float M = __int_as_float(*(volatile int*)slot);
    float inv = (M > 0.f) ? 127.f / M : 0.f;
#pragma unroll
    for (int j = 0; j < 8; j++) {
        int n = n0 + j * 8 + 2 * (lane & 3);
#pragma unroll
        for (int i = 0; i < 2; i++) {
            int* dd = d[i * 8 + j];
            int r0 = m0 + 16 * i + (lane >> 2);
            int a1, a2, b1, b2;
            quant2(__int_as_float(dd[0]), inv, a1, a2);
            quant2(__int_as_float(dd[1]), inv, b1, b2);
            *(unsigned short*)(smc + OFF_A1 + apos8(r0, n)) = (unsigned short)pk2(b1, a1);
            *(unsigned short*)(smc + OFF_A2 + apos8(r0, n)) = (unsigned short)pk2(b2, a2);
            quant2(__int_as_float(dd[2]), inv, a1, a2);
            quant2(__int_as_float(dd[3]), inv, b1, b2);
            *(unsigned short*)(smc + OFF_A1 + apos8(r0 + 8, n)) = (unsigned short)pk2(b1, a1);
            *(unsigned short*)(smc + OFF_A2 + apos8(r0 + 8, n)) = (unsigned short)pk2(b2, a2);
        }
    }
    __syncthreads();
}

// load X[64,256] fp32 -> tile max -> two-level int8 into A planes
__device__ void stage_Xq(char* smc, const float* __restrict__ Xg, int e0,
                         int tid, int lane, int* slot) {
    int r = tid >> 2, qq = tid & 3;
    const float4* xr = (const float4*)(Xg + (size_t)(e0 + r) * 256) + qq * 16;
    float m = 0.f;
#pragma unroll
    for (int j = 0; j < 16; j++) {
        float4 v = xr[j];
        m = fmaxf(m, fmaxf(fmaxf(fabsf(v.x), fabsf(v.y)), fmaxf(fabsf(v.z), fabsf(v.w))));
    }
#pragma unroll
    for (int s = 16; s; s >>= 1) m = fmaxf(m, __shfl_xor_sync(0xffffffffu, m, s));
    if (lane == 0) atomicMax(slot, __float_as_int(m));
    __syncthreads();
    float M = __int_as_float(*(volatile int*)slot);
    float inv = (M > 0.f) ? 127.f / M : 0.f;
#pragma unroll
    for (int j = 0; j < 16; j++) {
        float4 v = xr[j];
        int q1[4], q2[4];
        quant2(v.x, inv, q1[0], q2[0]);
        quant2(v.y, inv, q1[1], q2[1]);
        quant2(v.z, inv, q1[2], q2[2]);
        quant2(v.w, inv, q1[3], q2[3]);
        uint32_t off = apos8(r, qq * 64 + j * 4);
        *(uint32_t*)(smc + OFF_A1 + off) = pk4(q1[3], q1[2], q1[1], q1[0]);
        *(uint32_t*)(smc + OFF_A2 + off) = pk4(q2[3], q2[2], q2[1], q2[0]);
    }
    __syncthreads();
}

// ---------------- main fused kernel ----------------
__global__ void __launch_bounds__(NTHREADS, 2)
gnn_main(const float* __restrict__ src, const float* __restrict__ nbr,
         const float* __restrict__ ppr, const int* __restrict__ pidx,
         float* __restrict__ out) {
    extern __shared__ char smraw[];
    char* smc = (char*)(((uintptr_t)smraw + 1023) & ~(uintptr_t)1023);
    const uint32_t SB = smem_u32(smc);
    const int tid = threadIdx.x;
    const int lane = tid & 31;
    const int w = tid >> 5, wm = w >> 2, wn = w & 3;
    const int m0 = wm * 32, n0h = wn * 64;
    const int lt = wm * 32 + lane;
    const int barid = wn + 1;
    const uint32_t gb = SB + OFF_B + (uint32_t)wn * 8192u;
    const int e0 = blockIdx.x * TILE;

    float* qsm  = (float*)(smc + OFF_Q);
    float* ksm  = (float*)(smc + OFF_KSM);
    float* wsm  = (float*)(smc + OFF_WSM);
    float* ewsm = (float*)(smc + OFF_EW);
    int*   gid  = (int*)(smc + OFF_GID);
    int*   slots = (int*)(smc + OFF_SC);

    const char* W0b1 = (const char*)gW0b1; const char* W0b2 = (const char*)gW0b2;
    const char* W1b1 = (const char*)gW1b1; const char* W1b2 = (const char*)gW1b2;
    const char* Qb1  = (const char*)gQb1;  const char* Qb2  = (const char*)gQb2;
    const char* Nb1  = (const char*)gNb1;  const char* Nb2  = (const char*)gNb2;

    if (tid < 8) slots[tid] = 0;
    __syncthreads();

    int d[16][4];
#define ZERO16() do { _Pragma("unroll") \
    for (int i = 0; i < 16; i++) { d[i][0]=0; d[i][1]=0; d[i][2]=0; d[i][3]=0; } } while (0)
#define ZERO8() do { _Pragma("unroll") \
    for (int i = 0; i < 8; i++) { d[i][0]=0; d[i][1]=0; d[i][2]=0; d[i][3]=0; } } while (0)

    // =========== PATH 0 (source) ===========
    cpyA(gb,         W0b1 + wn * 2048,        2048, lt);   // bootstrap A-chunks 0,1
    cpyA(gb + 4096u, W0b1 + 8192 + wn * 2048, 2048, lt);
    stage_Xq(smc, src, e0, tid, lane, &slots[0]);

    ZERO16();
    layer_q<8>(SB, gb, W0b1, W0b2, 8192, wn * 2048, 8,
               W1b1, 8192, wn * 2048, 2048, d, m0, 0, lane, lt, barid);
    epi_q(smc, d, m0, n0h, lane, __int_as_float(slots[0]), gS0, &slots[1]);

    ZERO16();
    layer_q<8>(SB, gb, W1b1, W1b2, 8192, wn * 2048, 8,
               Qb1 + 2 * wn * 1024, 1024, 0, 1024, d, m0, 0, lane, lt, barid);
    epi_q(smc, d, m0, n0h, lane, __int_as_float(slots[1]), gS1, &slots[2]);

    // =========== q final: K-split across groups (2 chunks each) ===========
    ZERO8();
    layer_q<4>(SB, gb, Qb1 + 2 * wn * 1024, Qb2 + 2 * wn * 1024, 1024, 0, 2,
               W0b1, 8192, wn * 2048, 2048, d, m0, 64 * wn, lane, lt, barid);
    __syncthreads();                       // all reads of A done -> A = f32 scratch
    {
        float sc = __int_as_float(slots[2]) * QC;
        float* part = (float*)smc + wn * 2048;
#pragma unroll
        for (int j = 0; j < 4; j++) {
            int n = j * 8 + 2 * (lane & 3);
            float s0 = gSf[n] * sc, s1 = gSf[n + 1] * sc;
#pragma unroll
            for (int i = 0; i < 2; i++) {
                int* dd = d[i * 4 + j];
                int m = m0 + 16 * i + (lane >> 2);
                part[m * 32 + n]           = (float)dd[0] * s0;
                part[m * 32 + n + 1]       = (float)dd[1] * s1;
                part[(m + 8) * 32 + n]     = (float)dd[2] * s0;
                part[(m + 8) * 32 + n + 1] = (float)dd[3] * s1;
            }
        }
        __syncthreads();
        float* P = (float*)smc;
        for (int i = tid; i < 2048; i += NTHREADS) {
            int m = i >> 5, n = i & 31;
            qsm[m * 33 + n] = P[i] + P[2048 + i] + P[4096 + i] + P[6144 + i];
        }
        __syncthreads();
    }

    // =========== PATH 1 (neighbor) ===========
    stage_Xq(smc, nbr, e0, tid, lane, &slots[3]);

    ZERO16();
    layer_q<8>(SB, gb, W0b1, W0b2, 8192, wn * 2048, 8,
               W1b1, 8192, wn * 2048, 2048, d, m0, 0, lane, lt, barid);
    epi_q(smc, d, m0, n0h, lane, __int_as_float(slots[3]), gS0, &slots[4]);

    ZERO16();
    layer_q<8>(SB, gb, W1b1, W1b2, 8192, wn * 2048, 8,
               Nb1, 3072, wn * 1024, (wn < 3) ? 1024 : 0, d, m0, 0, lane, lt, barid);
    epi_q(smc, d, m0, n0h, lane, __int_as_float(slots[4]), gS1, &slots[5]);

    // =========== neighbor final: N=96 [x_n(64) | k(32)], groups 0..2 ======
    ZERO8();
    if (wn < 3) {
        layer_q<4>(SB, gb, Nb1, Nb2, 3072, wn * 1024, 8,
                   (const char*)0, 0, 0, 0, d, m0, 0, lane, lt, barid);
    }
    __syncthreads();                       // finals done; B region reusable
    {
        float scn = __int_as_float(slots[5]) * QC;
        if (wn == 2) {                      // k -> ksm (image cols 64..95)
#pragma unroll
            for (int j = 0; j < 4; j++) {
                int h = j * 8 + 2 * (lane & 3);
                float s0 = gSf[96 + h] * scn, s1 = gSf[97 + h] * scn;
#pragma unroll
                for (int i = 0; i < 2; i++) {
                    int* dd = d[i * 4 + j];
                    int m = m0 + 16 * i + (lane >> 2);
                    ksm[m * 33 + h]           = (float)dd[0] * s0;
                    ksm[m * 33 + h + 1]       = (float)dd[1] * s1;
                    ksm[(m + 8) * 33 + h]     = (float)dd[2] * s0;
                    ksm[(m + 8) * 33 + h + 1] = (float)dd[3] * s1;
                }
            }
        } else if (wn < 2) {                // x_n -> wsm (image cols 0..63)
#pragma unroll
            for (int j = 0; j < 4; j++) {
                int cc = wn * 32 + j * 8 + 2 * (lane & 3);
                float s0 = gSf[32 + cc] * scn, s1 = gSf[33 + cc] * scn;
#pragma unroll
                for (int i = 0; i < 2; i++) {
                    int* dd = d[i * 4 + j];
                    int m = m0 + 16 * i + (lane >> 2);
                    wsm[m * 65 + cc]           = (float)dd[0] * s0;
                    wsm[m * 65 + cc + 1]       = (float)dd[1] * s1;
                    wsm[(m + 8) * 65 + cc]     = (float)dd[2] * s0;
                    wsm[(m + 8) * 65 + cc + 1] = (float)dd[3] * s1;
                }
            }
        }
    }
    __syncthreads();
    if (tid < TILE) {                       // attention scalar
        float s = 0.f;
#pragma unroll
        for (int h = 0; h < HSZ; h++) s += qsm[tid * 33 + h] * ksm[tid * 33 + h];
        ewsm[tid] = ppr[e0 + tid] / (1.f + expf(-s));
        gid[tid]  = pidx[e0 + tid];
    }
    __syncthreads();
    {   // RLE segmented atomics (ppr_idx sorted): 4 strips x 16 edges x 64 cols
        const int col = tid & 63;
        const int base = (tid >> 6) * 16;
        float acc = 0.f;
        int prev = gid[base];
#pragma unroll
        for (int i = 0; i < 16; i++) {
            int g = gid[base + i];
            if (g != prev) {
                atomicAdd(out + (size_t)prev * NCLS + col, acc);
                acc = 0.f;
                prev = g;
            }
            acc += wsm[(base + i) * 65 + col] * ewsm[base + i];
        }
        atomicAdd(out + (size_t)prev * NCLS + col, acc);
    }
}

// ---------------- launch ----------------
extern "C" void kernel_launch(void* const* d_in, const int* in_sizes, int n_in,
                              void* d_out, int out_size) {
    const float* src  = (const float*)d_in[0];
    const float* nbr  = (const float*)d_in[1];
    const float* ppr  = (const float*)d_in[2];
    const int*   pidx = (const int*)  d_in[3];
    // d_in[4] = neighbor_idx (unused by reference)
    const float* W0   = (const float*)d_in[5];
    const float* W1   = (const float*)d_in[6];
    const float* W2   = (const float*)d_in[7];
    const float* Wqk  = (const float*)d_in[8];
    const float* Wk   = (const float*)d_in[9];
    float* out = (float*)d_out;

    cudaFuncSetAttribute(gnn_main, cudaFuncAttributeMaxDynamicSharedMemorySize,
                         (int)SMEM_REQ);

    prep_fold<<<128, 256>>>(W2, Wqk, Wk);
    prep_scales<<<3, 256>>>(W0, W1);
    prep_quant<<<640, 256>>>(W0, W1);
    zero_out_kernel<<<(out_size + 255) / 256, 256>>>(out, out_size);
    gnn_main<<<NBLK, NTHREADS, SMEM_REQ>>>(src, nbr, ppr, pidx, out);
}

// round 14
// speedup vs baseline: 2.2883x; 2.2883x over previous
#include <cuda_runtime.h>
#include <cuda_bf16.h>
#include <math.h>
#include <stdint.h>

// ---------------- problem constants ----------------
#define E_TOT   400000
#define TILE    64
#define NBLK    (E_TOT / TILE)   // 6250
#define NCLS    64
#define HSZ     32
#define NTHREADS 256

// ---------------- smem layout (from 1024-aligned base) ----------------
#define OFF_AH   0u          // A hi : 64 rows x 512B = 32KB
#define OFF_AL   32768u      // A lo : 32KB
#define OFF_B    65536u      // 4 groups x 2 bufs x 4KB = 32KB
#define OFF_Q    98304u      // q f32 [64][33] = 8448B
#define OFF_EW   106752u     // ew f32 [64]
#define OFF_GID  107008u     // gid int [64]
#define OFF_KSM  65536u      // k  f32 [64][33] (alias over B, post-GEMM)
#define OFF_WSM  74240u      // xn f32 [64][65] (alias over B, post-GEMM)
#define SMEM_REQ (107264u + 1024u)

// ---------------- pre-split, pre-swizzled weights ----------------
// Kc=16 chunks; within chunk, row n (32B): byte n*32 + ((kk*2)^(((n>>2)&1)<<4))
__device__ unsigned short gB0h[65536], gB0l[65536];   // layer0: 16 chunks x 8KB
__device__ unsigned short gB1h[65536], gB1l[65536];   // layer1
__device__ unsigned short gBqh[8192],  gBql[8192];    // q image N=32 (W2@Wqk): 16 x 1KB
__device__ unsigned short gBnh[24576], gBnl[24576];   // final N=96 [W2 | W2@Wk]: 16 x 3KB

// ---------------- helpers ----------------
__device__ __forceinline__ uint32_t smem_u32(const void* p) {
    uint32_t a;
    asm("{ .reg .u64 t; cvta.to.shared.u64 t, %1; cvt.u32.u64 %0, t; }"
        : "=r"(a) : "l"(p));
    return a;
}
__device__ __forceinline__ void split2(float a, float b, uint32_t& hi, uint32_t& lo) {
    uint32_t h;
    asm("cvt.rn.bf16x2.f32 %0, %1, %2;" : "=r"(h) : "f"(b), "f"(a));
    float ha = __uint_as_float(h << 16);
    float hb = __uint_as_float(h & 0xffff0000u);
    asm("cvt.rn.bf16x2.f32 %0, %1, %2;" : "=r"(lo) : "f"(b - hb), "f"(a - ha));
    hi = h;
}
__device__ __forceinline__ void split1(float x, unsigned short& hu, unsigned short& lu) {
    __nv_bfloat16 hb = __float2bfloat16(x);
    hu = *reinterpret_cast<unsigned short*>(&hb);
    float hf = __uint_as_float((uint32_t)hu << 16);
    __nv_bfloat16 lb = __float2bfloat16(x - hf);
    lu = *reinterpret_cast<unsigned short*>(&lb);
}
__device__ __forceinline__ void ldsm4(uint32_t addr, uint32_t& r0, uint32_t& r1,
                                      uint32_t& r2, uint32_t& r3) {
    asm volatile("ldmatrix.sync.aligned.m8n8.x4.shared.b16 {%0,%1,%2,%3}, [%4];"
                 : "=r"(r0), "=r"(r1), "=r"(r2), "=r"(r3) : "r"(addr));
}
__device__ __forceinline__ void mma16816(float* d, const uint32_t* a,
                                         uint32_t b0, uint32_t b1) {
    asm volatile("mma.sync.aligned.m16n8k16.row.col.f32.bf16.bf16.f32 "
                 "{%0,%1,%2,%3}, {%4,%5,%6,%7}, {%8,%9}, {%0,%1,%2,%3};"
                 : "+f"(d[0]), "+f"(d[1]), "+f"(d[2]), "+f"(d[3])
                 : "r"(a[0]), "r"(a[1]), "r"(a[2]), "r"(a[3]), "r"(b0), "r"(b1));
}
__device__ __forceinline__ void cpa16(uint32_t s, const void* g) {
    asm volatile("cp.async.cg.shared.global [%0], [%1], 16;" :: "r"(s), "l"(g));
}
#define CP_COMMIT() asm volatile("cp.async.commit_group;")
#define CP_WAIT1()  asm volatile("cp.async.wait_group 1;" ::: "memory")
#define BARG(id)    asm volatile("bar.sync %0, 64;" :: "r"(id) : "memory")

// A swizzle: row = 512B, conflict-free ldmatrix
__device__ __forceinline__ uint32_t aoff(int row, int kb) {
    return (uint32_t)row * 512u + (uint32_t)(kb ^ ((row & 7) << 4));
}
// B swizzle within slice/chunk: row = 32B
__device__ __forceinline__ uint32_t bxor(int r, int lh) {
    return (uint32_t)r * 32u + (uint32_t)(lh ^ (((r >> 2) & 1) << 4));
}

// ---------------- setup kernels ----------------
__global__ void prep_w01(const float* __restrict__ W0, const float* __restrict__ W1) {
    int idx = blockIdx.x * blockDim.x + threadIdx.x;   // 131072
    int layer = idx >> 16;
    int rem = idx & 65535;
    int k = rem >> 8, n = rem & 255;
    const float* W = layer ? W1 : W0;
    unsigned short hu, lu;
    split1(W[k * 256 + n], hu, lu);
    int c = k >> 4, kk = k & 15;
    uint32_t bp = (uint32_t)c * 8192u + bxor(n, kk * 2);
    (layer ? gB1h : gB0h)[bp >> 1] = hu;
    (layer ? gB1l : gB0l)[bp >> 1] = lu;
}

__global__ void prep_wf(const float* __restrict__ W2, const float* __restrict__ Wqk,
                        const float* __restrict__ Wk) {
    int idx = blockIdx.x * blockDim.x + threadIdx.x;   // 32768
    int k = idx >> 7, n = idx & 127;
    int c = k >> 4, kk = k & 15;
    unsigned short hu, lu;
    if (n < 32) {
        float s = 0.f;
        for (int cc = 0; cc < 64; cc++) s += W2[k * 64 + cc] * Wqk[cc * 32 + n];
        split1(s, hu, lu);
        uint32_t bp = (uint32_t)c * 1024u + bxor(n, kk * 2);
        gBqh[bp >> 1] = hu; gBql[bp >> 1] = lu;
    } else {
        int m = n - 32;
        float v;
        if (m < 64) v = W2[k * 64 + m];
        else {
            float s = 0.f;
            for (int cc = 0; cc < 64; cc++) s += W2[k * 64 + cc] * Wk[cc * 32 + (m - 64)];
            v = s;
        }
        split1(v, hu, lu);
        uint32_t bp = (uint32_t)c * 3072u + bxor(m, kk * 2);
        gBnh[bp >> 1] = hu; gBnl[bp >> 1] = lu;
    }
}

__global__ void zero_out_kernel(float* __restrict__ out, int n) {
    int i = blockIdx.x * blockDim.x + threadIdx.x;
    if (i < n) out[i] = 0.f;
}

// ---------------- GEMM pieces ----------------
// one Kc=16 chunk: D += (Ah+Al)@(Bh+Bl), 3 passes; buf = [hi 2KB | lo 2KB]
template<int NF>
__device__ __forceinline__ void compute_grp(uint32_t SB, uint32_t buf,
                                            float (*d)[4], int m0, int lane, int kbA0) {
    const int lr = lane & 15;
    const int lh = (lane >> 4) * 16;
    const int kbA = kbA0 + lh;
    uint32_t ah[2][4], al[2][4];
#pragma unroll
    for (int i = 0; i < 2; i++) {
        int row = m0 + 16 * i + lr;
        ldsm4(SB + OFF_AH + aoff(row, kbA), ah[i][0], ah[i][1], ah[i][2], ah[i][3]);
        ldsm4(SB + OFF_AL + aoff(row, kbA), al[i][0], al[i][1], al[i][2], al[i][3]);
    }
    uint32_t b[NF][2];
#pragma unroll
    for (int jj = 0; jj < NF / 2; jj++) {
        int r = jj * 16 + lr;
        uint32_t r0, r1, r2, r3;
        ldsm4(buf + bxor(r, lh), r0, r1, r2, r3);
        b[2 * jj][0] = r0; b[2 * jj][1] = r2;
        b[2 * jj + 1][0] = r1; b[2 * jj + 1][1] = r3;
    }
#pragma unroll
    for (int i = 0; i < 2; i++)
#pragma unroll
        for (int j = 0; j < NF; j++) mma16816(d[i * NF + j], ah[i], b[j][0], b[j][1]);
#pragma unroll
    for (int i = 0; i < 2; i++)
#pragma unroll
        for (int j = 0; j < NF; j++) mma16816(d[i * NF + j], al[i], b[j][0], b[j][1]);
#pragma unroll
    for (int jj = 0; jj < NF / 2; jj++) {
        int r = jj * 16 + lr;
        uint32_t r0, r1, r2, r3;
        ldsm4(buf + 2048u + bxor(r, lh), r0, r1, r2, r3);
        b[2 * jj][0] = r0; b[2 * jj][1] = r2;
        b[2 * jj + 1][0] = r1; b[2 * jj + 1][1] = r3;
    }
#pragma unroll
    for (int i = 0; i < 2; i++)
#pragma unroll
        for (int j = 0; j < NF; j++) mma16816(d[i * NF + j], ah[i], b[j][0], b[j][1]);
}

// group copies its own slice (hi+lo) + commit (1 group)
__device__ __forceinline__ void copy_slice(uint32_t dst, const char* srcH,
                                           const char* srcL, int nbytes, int lt) {
    for (int i = lt * 16; i < nbytes; i += 64 * 16) {
        cpa16(dst + i, srcH + i);
        cpa16(dst + 2048u + i, srcL + i);
    }
    CP_COMMIT();
}

// full layer: 16 chunks, group-private double buffer, named barriers.
// pre: chunks 0,1 already committed into buf0,buf1.
// At c=14/15 prefetches next image chunks 0,1 (or empty-commits).
template<int NF>
__device__ void run_layer_grp(uint32_t SB, uint32_t gb,
        const char* gH, const char* gL, int chunkB, int sliceOff, int sliceB,
        bool pre, const char* nxH, const char* nxL, int nxChunkB, int nxSliceOff,
        int nxSliceB, float (*d)[4], int m0, int lane, int lt, int barid) {
    if (!pre) {
        copy_slice(gb,         gH + sliceOff,          gL + sliceOff,          sliceB, lt);
        copy_slice(gb + 4096u, gH + chunkB + sliceOff, gL + chunkB + sliceOff, sliceB, lt);
    }
#pragma unroll 1
    for (int c = 0; c < 16; c++) {
        CP_WAIT1();
        BARG(barid);
        compute_grp<NF>(SB, gb + (c & 1) * 4096u, d, m0, lane, c * 32);
        BARG(barid);
        if (c < 14) {
            copy_slice(gb + (c & 1) * 4096u, gH + (c + 2) * chunkB + sliceOff,
                       gL + (c + 2) * chunkB + sliceOff, sliceB, lt);
        } else if (nxSliceB) {
            int cc = c - 14;
            copy_slice(gb + (cc & 1) * 4096u, nxH + cc * nxChunkB + nxSliceOff,
                       nxL + cc * nxChunkB + nxSliceOff, nxSliceB, lt);
        } else {
            CP_COMMIT();
        }
    }
}

// relu + split -> next layer's A
__device__ __forceinline__ void epi_hidden(char* smc, float (*d)[4], int m0, int n0, int lane) {
#pragma unroll
    for (int i = 0; i < 2; i++)
#pragma unroll
        for (int j = 0; j < 8; j++) {
            float* dd = d[i * 8 + j];
            int n = n0 + j * 8 + 2 * (lane & 3);
            int kb = n * 2;
            int r0 = m0 + 16 * i + (lane >> 2);
            uint32_t hi, lo;
            split2(fmaxf(dd[0], 0.f), fmaxf(dd[1], 0.f), hi, lo);
            *(uint32_t*)(smc + OFF_AH + aoff(r0, kb)) = hi;
            *(uint32_t*)(smc + OFF_AL + aoff(r0, kb)) = lo;
            split2(fmaxf(dd[2], 0.f), fmaxf(dd[3], 0.f), hi, lo);
            *(uint32_t*)(smc + OFF_AH + aoff(r0 + 8, kb)) = hi;
            *(uint32_t*)(smc + OFF_AL + aoff(r0 + 8, kb)) = lo;
        }
}

// load X[64,256] fp32, split, store to A hi/lo
__device__ __forceinline__ void stage_X(char* smc, const float* __restrict__ Xg,
                                        int e0, int tid) {
    int r = tid >> 2, qq = tid & 3;
    const float4* xr = (const float4*)(Xg + (size_t)(e0 + r) * 256) + qq * 16;
#pragma unroll
    for (int j = 0; j < 16; j++) {
        float4 v = xr[j];
        uint32_t h0, l0, h1, l1;
        split2(v.x, v.y, h0, l0);
        split2(v.z, v.w, h1, l1);
        int kb = (qq * 64 + j * 4) * 2;
        uint32_t off = aoff(r, kb);
        *(uint2*)(smc + OFF_AH + off) = make_uint2(h0, h1);
        *(uint2*)(smc + OFF_AL + off) = make_uint2(l0, l1);
    }
}

// ---------------- main fused kernel ----------------
__global__ void __launch_bounds__(NTHREADS, 2)
gnn_main(const float* __restrict__ src, const float* __restrict__ nbr,
         const float* __restrict__ ppr, const int* __restrict__ pidx,
         float* __restrict__ out) {
    extern __shared__ char smraw[];
    char* smc = (char*)(((uintptr_t)smraw + 1023) & ~(uintptr_t)1023);
    const uint32_t SB = smem_u32(smc);
    const int tid = threadIdx.x;
    const int lane = tid & 31;
    const int w = tid >> 5, wm = w >> 2, wn = w & 3;
    const int m0 = wm * 32, n0h = wn * 64;
    const int lt = wm * 32 + lane;        // thread index within wn-group (0..63)
    const int barid = wn + 1;
    const uint32_t gb = SB + OFF_B + (uint32_t)wn * 8192u;
    const int e0 = blockIdx.x * TILE;

    // ---- anti-lockstep desync: odd CTAs burn ~1200 dependent-ALU cycles ----
    // (2 CTAs/SM run identical phase structures; staggering them lets one
    //  CTA's MMA phase overlap the other's copy/epilogue phase.)
    if (blockIdx.x & 1) {
        float v = (float)(tid + 1);
#pragma unroll 1
        for (int i = 0; i < 300; i++) v = fmaf(v, 1.0000001f, 1e-30f);
        if (v == 123456.78f) ((volatile float*)smc)[0] = v;   // never true; keeps chain
    }

    float* qsm  = (float*)(smc + OFF_Q);
    float* ksm  = (float*)(smc + OFF_KSM);
    float* wsm  = (float*)(smc + OFF_WSM);
    float* ewsm = (float*)(smc + OFF_EW);
    int*   gid  = (int*)(smc + OFF_GID);

    const char* B0h = (const char*)gB0h; const char* B0l = (const char*)gB0l;
    const char* B1h = (const char*)gB1h; const char* B1l = (const char*)gB1l;
    const char* Qh  = (const char*)gBqh; const char* Ql  = (const char*)gBql;
    const char* Nh  = (const char*)gBnh; const char* Nl  = (const char*)gBnl;

    float d[16][4];

    // =========== PATH 0 (source) ===========
    stage_X(smc, src, e0, tid);
    __syncthreads();
#pragma unroll
    for (int i = 0; i < 16; i++) { d[i][0] = d[i][1] = d[i][2] = d[i][3] = 0.f; }
    run_layer_grp<8>(SB, gb, B0h, B0l, 8192, wn * 2048, 2048, false,
                     B1h, B1l, 8192, wn * 2048, 2048, d, m0, lane, lt, barid);
    __syncthreads();
    epi_hidden(smc, d, m0, n0h, lane);
    __syncthreads();
#pragma unroll
    for (int i = 0; i < 16; i++) { d[i][0] = d[i][1] = d[i][2] = d[i][3] = 0.f; }
    run_layer_grp<8>(SB, gb, B1h, B1l, 8192, wn * 2048, 2048, true,
                     Qh + wn * 4096, Ql + wn * 4096, 1024, 0, 1024,
                     d, m0, lane, lt, barid);
    __syncthreads();
    epi_hidden(smc, d, m0, n0h, lane);
    __syncthreads();

    // =========== q final: K-split across groups (4 chunks each) ===========
    {
#pragma unroll
        for (int i = 0; i < 8; i++) { d[i][0] = d[i][1] = d[i][2] = d[i][3] = 0.f; }
#pragma unroll 1
        for (int c = 0; c < 4; c++) {
            CP_WAIT1();
            BARG(barid);
            compute_grp<4>(SB, gb + (c & 1) * 4096u, d, m0, lane, (4 * wn + c) * 32);
            BARG(barid);
            if (c < 2) {
                copy_slice(gb + (c & 1) * 4096u, Qh + (4 * wn + c + 2) * 1024,
                           Ql + (4 * wn + c + 2) * 1024, 1024, lt);
            } else {
                int cc = c - 2;
                copy_slice(gb + (cc & 1) * 4096u, B0h + cc * 8192 + wn * 2048,
                           B0l + cc * 8192 + wn * 2048, 2048, lt);
            }
        }
        __syncthreads();                   // all reads of A done -> AH reusable
        float* part = (float*)(smc + OFF_AH) + wn * 2048;
#pragma unroll
        for (int i = 0; i < 2; i++)
#pragma unroll
            for (int j = 0; j < 4; j++) {
                int n = j * 8 + 2 * (lane & 3);
                int m = m0 + 16 * i + (lane >> 2);
                float* dd = d[i * 4 + j];
                part[m * 32 + n]           = dd[0];
                part[m * 32 + n + 1]       = dd[1];
                part[(m + 8) * 32 + n]     = dd[2];
                part[(m + 8) * 32 + n + 1] = dd[3];
            }
        __syncthreads();
        float* P = (float*)(smc + OFF_AH);
        for (int i = tid; i < 2048; i += NTHREADS) {
            int m = i >> 5, n = i & 31;
            qsm[m * 33 + n] = P[i] + P[2048 + i] + P[4096 + i] + P[6144 + i];
        }
        __syncthreads();
    }

    // =========== PATH 1 (neighbor) ===========
    stage_X(smc, nbr, e0, tid);
    __syncthreads();
#pragma unroll
    for (int i = 0; i < 16; i++) { d[i][0] = d[i][1] = d[i][2] = d[i][3] = 0.f; }
    run_layer_grp<8>(SB, gb, B0h, B0l, 8192, wn * 2048, 2048, true,
                     B1h, B1l, 8192, wn * 2048, 2048, d, m0, lane, lt, barid);
    __syncthreads();
    epi_hidden(smc, d, m0, n0h, lane);
    __syncthreads();
#pragma unroll
    for (int i = 0; i < 16; i++) { d[i][0] = d[i][1] = d[i][2] = d[i][3] = 0.f; }
    run_layer_grp<8>(SB, gb, B1h, B1l, 8192, wn * 2048, 2048, true,
                     Nh, Nl, 3072, wn * 1024, (wn < 3) ? 1024 : 0,
                     d, m0, lane, lt, barid);
    __syncthreads();
    epi_hidden(smc, d, m0, n0h, lane);
    __syncthreads();

    // =========== neighbor final: N=96 [x_n(64) | k(32)], groups 0..2 ======
#pragma unroll
    for (int i = 0; i < 8; i++) { d[i][0] = d[i][1] = d[i][2] = d[i][3] = 0.f; }
    if (wn < 3) {
        run_layer_grp<4>(SB, gb, Nh, Nl, 3072, wn * 1024, 1024, true,
                         (const char*)0, (const char*)0, 0, 0, 0,
                         d, m0, lane, lt, barid);
    }
    __syncthreads();                       // finals done; B region reusable
    if (wn == 2) {                          // k -> ksm
#pragma unroll
        for (int i = 0; i < 2; i++)
#pragma unroll
            for (int j = 0; j < 4; j++) {
                int h = j * 8 + 2 * (lane & 3);
                int m = m0 + 16 * i + (lane >> 2);
                float* dd = d[i * 4 + j];
                ksm[m * 33 + h]           = dd[0];
                ksm[m * 33 + h + 1]       = dd[1];
                ksm[(m + 8) * 33 + h]     = dd[2];
                ksm[(m + 8) * 33 + h + 1] = dd[3];
            }
    } else if (wn < 2) {                    // x_n -> wsm
#pragma unroll
        for (int i = 0; i < 2; i++)
#pragma unroll
            for (int j = 0; j < 4; j++) {
                int cc = wn * 32 + j * 8 + 2 * (lane & 3);
                int m = m0 + 16 * i + (lane >> 2);
                float* dd = d[i * 4 + j];
                wsm[m * 65 + cc]           = dd[0];
                wsm[m * 65 + cc + 1]       = dd[1];
                wsm[(m + 8) * 65 + cc]     = dd[2];
                wsm[(m + 8) * 65 + cc + 1] = dd[3];
            }
    }
    __syncthreads();
    if (tid < TILE) {                       // attention scalar
        float s = 0.f;
#pragma unroll
        for (int h = 0; h < HSZ; h++) s += qsm[tid * 33 + h] * ksm[tid * 33 + h];
        ewsm[tid] = ppr[e0 + tid] / (1.f + expf(-s));
        gid[tid]  = pidx[e0 + tid];
    }
    __syncthreads();
    {   // RLE segmented atomics (ppr_idx sorted): 4 strips x 16 edges x 64 cols
        const int col = tid & 63;
        const int base = (tid >> 6) * 16;
        float acc = 0.f;
        int prev = gid[base];
#pragma unroll
        for (int i = 0; i < 16; i++) {
            int g = gid[base + i];
            if (g != prev) {
                atomicAdd(out + (size_t)prev * NCLS + col, acc);
                acc = 0.f;
                prev = g;
            }
            acc += wsm[(base + i) * 65 + col] * ewsm[base + i];
        }
        atomicAdd(out + (size_t)prev * NCLS + col, acc);
    }
}

// ---------------- launch ----------------
extern "C" void kernel_launch(void* const* d_in, const int* in_sizes, int n_in,
                              void* d_out, int out_size) {
    const float* src  = (const float*)d_in[0];
    const float* nbr  = (const float*)d_in[1];
    const float* ppr  = (const float*)d_in[2];
    const int*   pidx = (const int*)  d_in[3];
    // d_in[4] = neighbor_idx (unused by reference)
    const float* W0   = (const float*)d_in[5];
    const float* W1   = (const float*)d_in[6];
    const float* W2   = (const float*)d_in[7];
    const float* Wqk  = (const float*)d_in[8];
    const float* Wk   = (const float*)d_in[9];
    float* out = (float*)d_out;

    cudaFuncSetAttribute(gnn_main, cudaFuncAttributeMaxDynamicSharedMemorySize,
                         (int)SMEM_REQ);

    prep_w01<<<512, 256>>>(W0, W1);
    prep_wf<<<128, 256>>>(W2, Wqk, Wk);
    zero_out_kernel<<<(out_size + 255) / 256, 256>>>(out, out_size);
    gnn_main<<<NBLK, NTHREADS, SMEM_REQ>>>(src, nbr, ppr, pidx, out);
}